// round 4
// baseline (speedup 1.0000x reference)
#include <cuda_runtime.h>
#include <cuda_bf16.h>
#include <cstdint>

#define NN 50000
#define EE 800000
#define EPP 200000
#define DIM 128
#define KK 256
#define MTILES ((NN + 127) / 128)

// ---------------- scratch ----------------------------------------------------
__device__ int   g_deg[NN];
__device__ int   g_rowptr[NN + 1];
__device__ int   g_cursor[NN];
__device__ int   g_csr_src[EE];
__device__ float g_h[NN * DIM];
__device__ float g_z[NN * DIM];
__device__ __nv_bfloat16 g_Ahi[NN * KK];      // [node][k]  k<128: agg, k>=128: feat
__device__ __nv_bfloat16 g_Alo[NN * KK];
__device__ __nv_bfloat16 g_Whi[2 * DIM * KK]; // [layer][n][k]  (Wcat transposed)
__device__ __nv_bfloat16 g_Wlo[2 * DIM * KK];

// split fp32 -> bf16 hi + bf16 lo, packed stores (4 values -> uint2 each)
__device__ __forceinline__ void split_store4(float4 v, __nv_bfloat16* hp, __nv_bfloat16* lp) {
    __nv_bfloat162 h0 = __floats2bfloat162_rn(v.x, v.y);
    __nv_bfloat162 h1 = __floats2bfloat162_rn(v.z, v.w);
    float lx = v.x - __bfloat162float(h0.x);
    float ly = v.y - __bfloat162float(h0.y);
    float lz = v.z - __bfloat162float(h1.x);
    float lw = v.w - __bfloat162float(h1.y);
    __nv_bfloat162 l0 = __floats2bfloat162_rn(lx, ly);
    __nv_bfloat162 l1 = __floats2bfloat162_rn(lz, lw);
    *(uint2*)hp = make_uint2(*(unsigned*)&h0, *(unsigned*)&h1);
    *(uint2*)lp = make_uint2(*(unsigned*)&l0, *(unsigned*)&l1);
}

__device__ __forceinline__ void split_store2(float a, float b, __nv_bfloat16* hp, __nv_bfloat16* lp) {
    __nv_bfloat162 h = __floats2bfloat162_rn(a, b);
    float la = a - __bfloat162float(h.x);
    float lb = b - __bfloat162float(h.y);
    __nv_bfloat162 l = __floats2bfloat162_rn(la, lb);
    *(unsigned*)hp = *(unsigned*)&h;
    *(unsigned*)lp = *(unsigned*)&l;
}

// ---------------- CSR build --------------------------------------------------
__global__ void k_zero_deg() {
    int i = blockIdx.x * blockDim.x + threadIdx.x;
    if (i < NN) g_deg[i] = 0;
}
__global__ void k_count(const int* __restrict__ dst) {
    int e = blockIdx.x * blockDim.x + threadIdx.x;
    if (e < EE) {
        unsigned d = (unsigned)dst[e];
        if (d < NN) atomicAdd(&g_deg[d], 1);
    }
}
__global__ void k_scan() {
    __shared__ int warp_sums[32];
    __shared__ int s_carry;
    int tid = threadIdx.x;
    if (tid == 0) s_carry = 0;
    __syncthreads();
    for (int base = 0; base < NN; base += 1024) {
        int i = base + tid;
        int v = (i < NN) ? g_deg[i] : 0;
        int x = v;
        #pragma unroll
        for (int o = 1; o < 32; o <<= 1) {
            int y = __shfl_up_sync(0xffffffffu, x, o);
            if ((tid & 31) >= o) x += y;
        }
        if ((tid & 31) == 31) warp_sums[tid >> 5] = x;
        __syncthreads();
        if (tid < 32) {
            int w = warp_sums[tid];
            #pragma unroll
            for (int o = 1; o < 32; o <<= 1) {
                int y = __shfl_up_sync(0xffffffffu, w, o);
                if (tid >= o) w += y;
            }
            warp_sums[tid] = w;
        }
        __syncthreads();
        int incl = x + ((tid >= 32) ? warp_sums[(tid >> 5) - 1] : 0) + s_carry;
        if (i < NN) {
            g_rowptr[i + 1] = incl;
            g_cursor[i] = incl - v;
        }
        __syncthreads();
        if (tid == 1023) s_carry = incl;
        __syncthreads();
    }
    if (tid == 0) g_rowptr[0] = 0;
}
__global__ void k_fill(const int* __restrict__ src, const int* __restrict__ dst) {
    int e = blockIdx.x * blockDim.x + threadIdx.x;
    if (e < EE) {
        unsigned d = (unsigned)dst[e];
        unsigned s = (unsigned)src[e];
        if (d < NN && s < NN) {
            int p = atomicAdd(&g_cursor[d], 1);
            if ((unsigned)p < EE) g_csr_src[p] = (int)s;
        }
    }
}

// ---------------- weight prepack: Wcat^T split to bf16 hi/lo -----------------
__global__ void k_prepackW(const float* __restrict__ W1l, const float* __restrict__ W1r,
                           const float* __restrict__ W2l, const float* __restrict__ W2r) {
    int idx = blockIdx.x * blockDim.x + threadIdx.x;  // 2*128*256 = 65536
    if (idx >= 2 * DIM * KK) return;
    int l = idx / (DIM * KK);
    int rem = idx - l * (DIM * KK);
    int n = rem / KK, k = rem % KK;
    const float* Wl = l ? W2l : W1l;
    const float* Wr = l ? W2r : W1r;
    float w = (k < DIM) ? Wl[k * DIM + n] : Wr[(k - DIM) * DIM + n];
    __nv_bfloat16 hi = __float2bfloat16(w);
    __nv_bfloat16 lo = __float2bfloat16(w - __bfloat162float(hi));
    g_Whi[idx] = hi;
    g_Wlo[idx] = lo;
}

// ---------------- x -> bf16 hi/lo into A[:,128:256] --------------------------
__global__ void k_convx(const float* __restrict__ x) {
    int idx = blockIdx.x * blockDim.x + threadIdx.x;  // NN*32
    if (idx >= NN * 32) return;
    int n = idx >> 5, c4 = idx & 31;
    float4 v = ((const float4*)x)[idx];
    size_t off = (size_t)n * KK + DIM + c4 * 4;
    split_store4(v, &g_Ahi[off], &g_Alo[off]);
}

// ---------------- mean aggregation (warp per node) ---------------------------
__global__ void k_agg(const float* __restrict__ feat_in, int use_h) {
    const float* feat = use_h ? g_h : feat_in;
    int warp_id = (blockIdx.x * blockDim.x + threadIdx.x) >> 5;
    int lane = threadIdx.x & 31;
    if (warp_id >= NN) return;
    int n = warp_id;
    int start = g_rowptr[n], end = g_rowptr[n + 1];
    const float4* f4 = (const float4*)feat;
    float4 acc = make_float4(0.f, 0.f, 0.f, 0.f);
    for (int base = start; base < end; base += 32) {
        int m = min(32, end - base);
        int sid = (lane < m) ? g_csr_src[base + lane] : 0;
        for (int t = 0; t < m; ++t) {
            int s = __shfl_sync(0xffffffffu, sid, t);
            float4 v = f4[s * 32 + lane];
            acc.x += v.x; acc.y += v.y; acc.z += v.z; acc.w += v.w;
        }
    }
    int d = end - start;
    float inv = 1.0f / (float)max(d, 1);
    acc.x *= inv; acc.y *= inv; acc.z *= inv; acc.w *= inv;
    size_t off = (size_t)n * KK + lane * 4;
    split_store4(acc, &g_Ahi[off], &g_Alo[off]);
}

// ---------------- bf16-split GEMM via mma.sync (HMMA) ------------------------
// out[128 rows] = A(128x256) @ Wcat(256x128) + b ; 3-term bf16 split, fp32 accum.
// 4 warps; warp w computes rows [w*32, w*32+32) x all 128 cols.
// smem: 4 tiles of 128 rows x 64 bf16 (16KB each): Ahi, Alo, Whi, Wlo.
// Swizzle: b32 unit u of row r stored at u ^ ((r&7)<<2) (uint4 group g -> g^(r&7)).

#define SMEM_MM 65536
#define T_AH 0
#define T_AL 16384
#define T_WH 32768
#define T_WL 49152

__device__ __forceinline__ uint32_t lds_swz(const char* sm, int toff, int r, int u) {
    return *(const uint32_t*)(sm + toff + r * 128 + ((u ^ ((r & 7) << 2)) << 2));
}

#define MMA_BF16(d, a, b0, b1)                                                    \
    asm volatile("mma.sync.aligned.m16n8k16.row.col.f32.bf16.bf16.f32 "           \
                 "{%0,%1,%2,%3}, {%4,%5,%6,%7}, {%8,%9}, {%0,%1,%2,%3};"          \
                 : "+f"((d)[0]), "+f"((d)[1]), "+f"((d)[2]), "+f"((d)[3])         \
                 : "r"((a)[0]), "r"((a)[1]), "r"((a)[2]), "r"((a)[3]),            \
                   "r"(b0), "r"(b1))

__global__ void __launch_bounds__(128) k_mm(const float* __restrict__ bias, int layer) {
    extern __shared__ char smem[];
    int tid = threadIdx.x, wid = tid >> 5, l = tid & 31;
    int row0 = blockIdx.x * 128;
    const __nv_bfloat16* Wh = g_Whi + (layer - 1) * DIM * KK;
    const __nv_bfloat16* Wl = g_Wlo + (layer - 1) * DIM * KK;

    float acc[32][4];
    #pragma unroll
    for (int i = 0; i < 32; ++i)
        acc[i][0] = acc[i][1] = acc[i][2] = acc[i][3] = 0.f;

    for (int chunk = 0; chunk < 4; ++chunk) {
        // load 4 tiles: 4096 uint4 slots total
        for (int i = tid; i < 4096; i += 128) {
            int t = i >> 10, s = i & 1023;
            int r = s >> 3, u4 = s & 7;
            uint4 v = make_uint4(0, 0, 0, 0);
            if (t < 2) {
                int gr = row0 + r;
                if (gr < NN) {
                    const __nv_bfloat16* p =
                        (t == 0 ? g_Ahi : g_Alo) + (size_t)gr * KK + chunk * 64 + u4 * 8;
                    v = *(const uint4*)p;
                }
            } else {
                const __nv_bfloat16* p =
                    (t == 2 ? Wh : Wl) + (size_t)r * KK + chunk * 64 + u4 * 8;
                v = *(const uint4*)p;
            }
            *(uint4*)(smem + t * 16384 + r * 128 + ((u4 ^ (r & 7)) << 4)) = v;
        }
        __syncthreads();

        #pragma unroll
        for (int ks = 0; ks < 4; ++ks) {
            int u = ks * 8 + (l & 3);
            uint32_t ah[2][4], al[2][4];
            #pragma unroll
            for (int mt = 0; mt < 2; ++mt) {
                int r = wid * 32 + mt * 16 + (l >> 2);
                ah[mt][0] = lds_swz(smem, T_AH, r, u);
                ah[mt][1] = lds_swz(smem, T_AH, r + 8, u);
                ah[mt][2] = lds_swz(smem, T_AH, r, u + 4);
                ah[mt][3] = lds_swz(smem, T_AH, r + 8, u + 4);
                al[mt][0] = lds_swz(smem, T_AL, r, u);
                al[mt][1] = lds_swz(smem, T_AL, r + 8, u);
                al[mt][2] = lds_swz(smem, T_AL, r, u + 4);
                al[mt][3] = lds_swz(smem, T_AL, r + 8, u + 4);
            }
            #pragma unroll
            for (int nt = 0; nt < 16; ++nt) {
                int rn = nt * 8 + (l >> 2);
                uint32_t bh0 = lds_swz(smem, T_WH, rn, u);
                uint32_t bh1 = lds_swz(smem, T_WH, rn, u + 4);
                uint32_t bl0 = lds_swz(smem, T_WL, rn, u);
                uint32_t bl1 = lds_swz(smem, T_WL, rn, u + 4);
                #pragma unroll
                for (int mt = 0; mt < 2; ++mt) {
                    MMA_BF16(acc[mt * 16 + nt], ah[mt], bh0, bh1);
                    MMA_BF16(acc[mt * 16 + nt], al[mt], bh0, bh1);
                    MMA_BF16(acc[mt * 16 + nt], ah[mt], bl0, bl1);
                }
            }
        }
        __syncthreads();
    }

    // epilogue: bias, (relu), write fp32 out; layer1 also writes bf16 split feat
    float* outp = (layer == 1) ? g_h : g_z;
    #pragma unroll
    for (int nt = 0; nt < 16; ++nt) {
        int c = nt * 8 + (l & 3) * 2;
        float2 b2 = *(const float2*)&bias[c];
        #pragma unroll
        for (int mt = 0; mt < 2; ++mt) {
            float* d = acc[mt * 16 + nt];
            int r1 = row0 + wid * 32 + mt * 16 + (l >> 2);
            float v0 = d[0] + b2.x, v1 = d[1] + b2.y;
            float v2 = d[2] + b2.x, v3 = d[3] + b2.y;
            if (layer == 1) {
                v0 = fmaxf(v0, 0.f); v1 = fmaxf(v1, 0.f);
                v2 = fmaxf(v2, 0.f); v3 = fmaxf(v3, 0.f);
            }
            if (r1 < NN) {
                *(float2*)&outp[(size_t)r1 * DIM + c] = make_float2(v0, v1);
                if (layer == 1) {
                    size_t o = (size_t)r1 * KK + DIM + c;
                    split_store2(v0, v1, &g_Ahi[o], &g_Alo[o]);
                }
            }
            if (r1 + 8 < NN) {
                *(float2*)&outp[(size_t)(r1 + 8) * DIM + c] = make_float2(v2, v3);
                if (layer == 1) {
                    size_t o = (size_t)(r1 + 8) * KK + DIM + c;
                    split_store2(v2, v3, &g_Ahi[o], &g_Alo[o]);
                }
            }
        }
    }
}

// ---------------- link prediction (warp per pred edge) -----------------------
__global__ void k_pred(const int* __restrict__ ps, const int* __restrict__ pd,
                       float* __restrict__ out) {
    int warp_id = (blockIdx.x * blockDim.x + threadIdx.x) >> 5;
    int lane = threadIdx.x & 31;
    if (warp_id >= EPP) return;
    const float4* z4 = (const float4*)g_z;
    unsigned a = (unsigned)ps[warp_id], b = (unsigned)pd[warp_id];
    if (a >= NN) a = 0;
    if (b >= NN) b = 0;
    float4 u = z4[(size_t)a * 32 + lane];
    float4 v = z4[(size_t)b * 32 + lane];
    float d = u.x * v.x + u.y * v.y + u.z * v.z + u.w * v.w;
    #pragma unroll
    for (int o = 16; o > 0; o >>= 1) d += __shfl_xor_sync(0xffffffffu, d, o);
    if (lane == 0) out[warp_id] = d;
}

// ---------------- launch -----------------------------------------------------
extern "C" void kernel_launch(void* const* d_in, const int* in_sizes, int n_in,
                              void* d_out, int out_size) {
    const float* x   = (const float*)d_in[0];
    const float* W1l = (const float*)d_in[1];
    const float* b1  = (const float*)d_in[2];
    const float* W1r = (const float*)d_in[3];
    const float* W2l = (const float*)d_in[4];
    const float* b2  = (const float*)d_in[5];
    const float* W2r = (const float*)d_in[6];
    const int* edge_index = (const int*)d_in[7];
    const int* pred_edges = (const int*)d_in[8];
    float* out = (float*)d_out;

    const int* src = edge_index;
    const int* dst = edge_index + EE;
    const int* ps = pred_edges;
    const int* pd = pred_edges + EPP;

    static int attr_done = 0;
    if (!attr_done) {
        cudaFuncSetAttribute(k_mm, cudaFuncAttributeMaxDynamicSharedMemorySize, SMEM_MM);
        attr_done = 1;
    }

    k_zero_deg<<<(NN + 255) / 256, 256>>>();
    k_count<<<(EE + 255) / 256, 256>>>(dst);
    k_scan<<<1, 1024>>>();
    k_fill<<<(EE + 255) / 256, 256>>>(src, dst);
    k_prepackW<<<(2 * DIM * KK + 255) / 256, 256>>>(W1l, W1r, W2l, W2r);
    k_convx<<<(NN * 32 + 255) / 256, 256>>>(x);

    k_agg<<<(NN * 32 + 255) / 256, 256>>>(x, 0);
    k_mm<<<MTILES, 128, SMEM_MM>>>(b1, 1);
    k_agg<<<(NN * 32 + 255) / 256, 256>>>(nullptr, 1);
    k_mm<<<MTILES, 128, SMEM_MM>>>(b2, 2);
    k_pred<<<(EPP * 32 + 255) / 256, 256>>>(ps, pd, out);
}

// round 5
// speedup vs baseline: 1.1448x; 1.1448x over previous
#include <cuda_runtime.h>
#include <cuda_bf16.h>
#include <cstdint>

#define NN 50000
#define EE 800000
#define EPP 200000
#define DIM 128
#define KK 256
#define MTILES ((NN + 127) / 128)

// ---------------- scratch ----------------------------------------------------
__device__ int   g_deg[NN];
__device__ int   g_rowptr[NN + 1];
__device__ int   g_cursor[NN];
__device__ int   g_csr_src[EE];
__device__ float g_h[NN * DIM];
__device__ float g_z[NN * DIM];
__device__ __nv_bfloat16 g_Ahi[NN * KK];      // [node][k]  k<128: agg, k>=128: feat
__device__ __nv_bfloat16 g_Alo[NN * KK];
__device__ __nv_bfloat16 g_Whi[2 * DIM * KK]; // [layer][n][k]  (Wcat transposed)
__device__ __nv_bfloat16 g_Wlo[2 * DIM * KK];

__device__ __forceinline__ uint32_t smem_u32(const void* p) {
    uint32_t a;
    asm("{ .reg .u64 t; cvta.to.shared.u64 t, %1; cvt.u32.u64 %0, t; }" : "=r"(a) : "l"(p));
    return a;
}

// split fp32 -> bf16 hi + bf16 lo, packed stores
__device__ __forceinline__ void split_store4(float4 v, __nv_bfloat16* hp, __nv_bfloat16* lp) {
    __nv_bfloat162 h0 = __floats2bfloat162_rn(v.x, v.y);
    __nv_bfloat162 h1 = __floats2bfloat162_rn(v.z, v.w);
    float lx = v.x - __bfloat162float(h0.x);
    float ly = v.y - __bfloat162float(h0.y);
    float lz = v.z - __bfloat162float(h1.x);
    float lw = v.w - __bfloat162float(h1.y);
    __nv_bfloat162 l0 = __floats2bfloat162_rn(lx, ly);
    __nv_bfloat162 l1 = __floats2bfloat162_rn(lz, lw);
    *(uint2*)hp = make_uint2(*(unsigned*)&h0, *(unsigned*)&h1);
    *(uint2*)lp = make_uint2(*(unsigned*)&l0, *(unsigned*)&l1);
}
__device__ __forceinline__ void split_store2(float a, float b, __nv_bfloat16* hp, __nv_bfloat16* lp) {
    __nv_bfloat162 h = __floats2bfloat162_rn(a, b);
    float la = a - __bfloat162float(h.x);
    float lb = b - __bfloat162float(h.y);
    __nv_bfloat162 l = __floats2bfloat162_rn(la, lb);
    *(unsigned*)hp = *(unsigned*)&h;
    *(unsigned*)lp = *(unsigned*)&l;
}

// ---------------- CSR build --------------------------------------------------
__global__ void k_zero_deg() {
    int i = blockIdx.x * blockDim.x + threadIdx.x;
    if (i < NN) g_deg[i] = 0;
}
__global__ void k_count(const int* __restrict__ dst) {
    int e = blockIdx.x * blockDim.x + threadIdx.x;
    if (e < EE) {
        unsigned d = (unsigned)dst[e];
        if (d < NN) atomicAdd(&g_deg[d], 1);
    }
}
__global__ void k_scan() {
    __shared__ int warp_sums[32];
    __shared__ int s_carry;
    int tid = threadIdx.x;
    if (tid == 0) s_carry = 0;
    __syncthreads();
    for (int base = 0; base < NN; base += 1024) {
        int i = base + tid;
        int v = (i < NN) ? g_deg[i] : 0;
        int x = v;
        #pragma unroll
        for (int o = 1; o < 32; o <<= 1) {
            int y = __shfl_up_sync(0xffffffffu, x, o);
            if ((tid & 31) >= o) x += y;
        }
        if ((tid & 31) == 31) warp_sums[tid >> 5] = x;
        __syncthreads();
        if (tid < 32) {
            int w = warp_sums[tid];
            #pragma unroll
            for (int o = 1; o < 32; o <<= 1) {
                int y = __shfl_up_sync(0xffffffffu, w, o);
                if (tid >= o) w += y;
            }
            warp_sums[tid] = w;
        }
        __syncthreads();
        int incl = x + ((tid >= 32) ? warp_sums[(tid >> 5) - 1] : 0) + s_carry;
        if (i < NN) {
            g_rowptr[i + 1] = incl;
            g_cursor[i] = incl - v;
        }
        __syncthreads();
        if (tid == 1023) s_carry = incl;
        __syncthreads();
    }
    if (tid == 0) g_rowptr[0] = 0;
}
__global__ void k_fill(const int* __restrict__ src, const int* __restrict__ dst) {
    int e = blockIdx.x * blockDim.x + threadIdx.x;
    if (e < EE) {
        unsigned d = (unsigned)dst[e];
        unsigned s = (unsigned)src[e];
        if (d < NN && s < NN) {
            int p = atomicAdd(&g_cursor[d], 1);
            if ((unsigned)p < EE) g_csr_src[p] = (int)s;
        }
    }
}

// ---------------- weight prepack: Wcat^T split to bf16 hi/lo -----------------
__global__ void k_prepackW(const float* __restrict__ W1l, const float* __restrict__ W1r,
                           const float* __restrict__ W2l, const float* __restrict__ W2r) {
    int idx = blockIdx.x * blockDim.x + threadIdx.x;
    if (idx >= 2 * DIM * KK) return;
    int l = idx / (DIM * KK);
    int rem = idx - l * (DIM * KK);
    int n = rem / KK, k = rem % KK;
    const float* Wl = l ? W2l : W1l;
    const float* Wr = l ? W2r : W1r;
    float w = (k < DIM) ? Wl[k * DIM + n] : Wr[(k - DIM) * DIM + n];
    __nv_bfloat16 hi = __float2bfloat16(w);
    __nv_bfloat16 lo = __float2bfloat16(w - __bfloat162float(hi));
    g_Whi[idx] = hi;
    g_Wlo[idx] = lo;
}

// ---------------- mean aggregation (warp per node); layer1 also splits x -----
__global__ void k_agg(const float* __restrict__ feat_in, int use_h) {
    const float* feat = use_h ? g_h : feat_in;
    int warp_id = (blockIdx.x * blockDim.x + threadIdx.x) >> 5;
    int lane = threadIdx.x & 31;
    if (warp_id >= NN) return;
    int n = warp_id;
    int start = g_rowptr[n], end = g_rowptr[n + 1];
    const float4* f4 = (const float4*)feat;
    float4 acc = make_float4(0.f, 0.f, 0.f, 0.f);
    for (int base = start; base < end; base += 32) {
        int m = min(32, end - base);
        int sid = (lane < m) ? g_csr_src[base + lane] : 0;
        for (int t = 0; t < m; ++t) {
            int s = __shfl_sync(0xffffffffu, sid, t);
            float4 v = f4[s * 32 + lane];
            acc.x += v.x; acc.y += v.y; acc.z += v.z; acc.w += v.w;
        }
    }
    int d = end - start;
    float inv = 1.0f / (float)max(d, 1);
    acc.x *= inv; acc.y *= inv; acc.z *= inv; acc.w *= inv;
    size_t off = (size_t)n * KK + lane * 4;
    split_store4(acc, &g_Ahi[off], &g_Alo[off]);
    if (!use_h) {  // layer 1: also split own feature x[n] into A[:,128:256]
        float4 v = f4[(size_t)n * 32 + lane];
        size_t o2 = (size_t)n * KK + DIM + lane * 4;
        split_store4(v, &g_Ahi[o2], &g_Alo[o2]);
    }
}

// ---------------- bf16-split GEMM via mma.sync + ldmatrix --------------------
// out[128 rows] = A(128x256) @ Wcat(256x128) + b ; 3-term bf16 split, fp32 accum.
// 8 warps; warp w = rows [w*16, w*16+16) x 128 cols.
// smem tiles [128 rows][64 bf16] = 16KB each: Ahi, Alo, Whi, Wlo.
// Store swizzle: 16B unit u of row r at (u ^ (r&7)).

#define SMEM_MM 65536
#define T_AH 0
#define T_AL 16384
#define T_WH 32768
#define T_WL 49152

__device__ __forceinline__ void ldsm_x4(uint32_t r[4], uint32_t saddr) {
    asm volatile("ldmatrix.sync.aligned.m8n8.x4.shared.b16 {%0,%1,%2,%3}, [%4];"
                 : "=r"(r[0]), "=r"(r[1]), "=r"(r[2]), "=r"(r[3]) : "r"(saddr));
}

#define MMA_BF16(d, a, b0, b1)                                                    \
    asm volatile("mma.sync.aligned.m16n8k16.row.col.f32.bf16.bf16.f32 "           \
                 "{%0,%1,%2,%3}, {%4,%5,%6,%7}, {%8,%9}, {%0,%1,%2,%3};"          \
                 : "+f"((d)[0]), "+f"((d)[1]), "+f"((d)[2]), "+f"((d)[3])         \
                 : "r"((a)[0]), "r"((a)[1]), "r"((a)[2]), "r"((a)[3]),            \
                   "r"(b0), "r"(b1))

__global__ void __launch_bounds__(256) k_mm(const float* __restrict__ bias, int layer) {
    extern __shared__ char smem[];
    uint32_t sb = smem_u32(smem);
    int tid = threadIdx.x, w = tid >> 5, l = tid & 31;
    int row0 = blockIdx.x * 128;
    const __nv_bfloat16* Wh = g_Whi + (layer - 1) * DIM * KK;
    const __nv_bfloat16* Wl = g_Wlo + (layer - 1) * DIM * KK;

    float acc[16][4];
    #pragma unroll
    for (int i = 0; i < 16; ++i)
        acc[i][0] = acc[i][1] = acc[i][2] = acc[i][3] = 0.f;

    // ldmatrix lane rows (fixed across k-steps)
    int rA = w * 16 + (l & 7) + ((l >> 3) & 1) * 8;  // A: blocks (m0-7,k0),(m8-15,k0),(m0-7,k1),(m8-15,k1)
    int uA_lane = (l >> 4) & 1;
    int rB_lane = (l & 7) + ((l >> 4) & 1) * 8;      // B: blocks (n0-7,k0),(n0-7,k1),(n8-15,k0),(n8-15,k1)
    int uB_lane = (l >> 3) & 1;
    uint32_t aA_base = sb + (uint32_t)(rA * 128);
    int swA = (rA & 7);

    for (int chunk = 0; chunk < 4; ++chunk) {
        // load 4 tiles: 4096 uint4 slots
        for (int i = tid; i < 4096; i += 256) {
            int t = i >> 10, s = i & 1023;
            int r = s >> 3, u4 = s & 7;
            uint4 v = make_uint4(0, 0, 0, 0);
            if (t < 2) {
                int gr = row0 + r;
                if (gr < NN) {
                    const __nv_bfloat16* p =
                        (t == 0 ? g_Ahi : g_Alo) + (size_t)gr * KK + chunk * 64 + u4 * 8;
                    v = *(const uint4*)p;
                }
            } else {
                const __nv_bfloat16* p =
                    (t == 2 ? Wh : Wl) + (size_t)r * KK + chunk * 64 + u4 * 8;
                v = *(const uint4*)p;
            }
            *(uint4*)(smem + t * 16384 + r * 128 + ((u4 ^ (r & 7)) << 4)) = v;
        }
        __syncthreads();

        #pragma unroll
        for (int ks = 0; ks < 4; ++ks) {
            int uA = ks * 2 + uA_lane;
            uint32_t ah[4], al[4];
            ldsm_x4(ah, aA_base + T_AH + (uint32_t)((uA ^ swA) << 4));
            ldsm_x4(al, aA_base + T_AL + (uint32_t)((uA ^ swA) << 4));
            int uB = ks * 2 + uB_lane;
            #pragma unroll
            for (int p = 0; p < 8; ++p) {
                int rB = p * 16 + rB_lane;
                uint32_t off = (uint32_t)(rB * 128 + (((uB ^ (rB & 7))) << 4));
                uint32_t bh[4], bl[4];
                ldsm_x4(bh, sb + T_WH + off);
                ldsm_x4(bl, sb + T_WL + off);
                MMA_BF16(acc[2 * p], ah, bh[0], bh[1]);
                MMA_BF16(acc[2 * p], al, bh[0], bh[1]);
                MMA_BF16(acc[2 * p], ah, bl[0], bl[1]);
                MMA_BF16(acc[2 * p + 1], ah, bh[2], bh[3]);
                MMA_BF16(acc[2 * p + 1], al, bh[2], bh[3]);
                MMA_BF16(acc[2 * p + 1], ah, bl[2], bl[3]);
            }
        }
        __syncthreads();
    }

    // epilogue: bias, (relu), write fp32 out; layer1 also writes bf16 split feat
    float* outp = (layer == 1) ? g_h : g_z;
    int r1 = row0 + w * 16 + (l >> 2);
    int r2 = r1 + 8;
    #pragma unroll
    for (int nt = 0; nt < 16; ++nt) {
        int c = nt * 8 + (l & 3) * 2;
        float2 b2 = *(const float2*)&bias[c];
        float* d = acc[nt];
        float v0 = d[0] + b2.x, v1 = d[1] + b2.y;
        float v2 = d[2] + b2.x, v3 = d[3] + b2.y;
        if (layer == 1) {
            v0 = fmaxf(v0, 0.f); v1 = fmaxf(v1, 0.f);
            v2 = fmaxf(v2, 0.f); v3 = fmaxf(v3, 0.f);
        }
        if (r1 < NN) {
            *(float2*)&outp[(size_t)r1 * DIM + c] = make_float2(v0, v1);
            if (layer == 1) {
                size_t o = (size_t)r1 * KK + DIM + c;
                split_store2(v0, v1, &g_Ahi[o], &g_Alo[o]);
            }
        }
        if (r2 < NN) {
            *(float2*)&outp[(size_t)r2 * DIM + c] = make_float2(v2, v3);
            if (layer == 1) {
                size_t o = (size_t)r2 * KK + DIM + c;
                split_store2(v2, v3, &g_Ahi[o], &g_Alo[o]);
            }
        }
    }
}

// ---------------- link prediction (warp per pred edge) -----------------------
__global__ void k_pred(const int* __restrict__ ps, const int* __restrict__ pd,
                       float* __restrict__ out) {
    int warp_id = (blockIdx.x * blockDim.x + threadIdx.x) >> 5;
    int lane = threadIdx.x & 31;
    if (warp_id >= EPP) return;
    const float4* z4 = (const float4*)g_z;
    unsigned a = (unsigned)ps[warp_id], b = (unsigned)pd[warp_id];
    if (a >= NN) a = 0;
    if (b >= NN) b = 0;
    float4 u = z4[(size_t)a * 32 + lane];
    float4 v = z4[(size_t)b * 32 + lane];
    float d = u.x * v.x + u.y * v.y + u.z * v.z + u.w * v.w;
    #pragma unroll
    for (int o = 16; o > 0; o >>= 1) d += __shfl_xor_sync(0xffffffffu, d, o);
    if (lane == 0) out[warp_id] = d;
}

// ---------------- launch -----------------------------------------------------
extern "C" void kernel_launch(void* const* d_in, const int* in_sizes, int n_in,
                              void* d_out, int out_size) {
    const float* x   = (const float*)d_in[0];
    const float* W1l = (const float*)d_in[1];
    const float* b1  = (const float*)d_in[2];
    const float* W1r = (const float*)d_in[3];
    const float* W2l = (const float*)d_in[4];
    const float* b2  = (const float*)d_in[5];
    const float* W2r = (const float*)d_in[6];
    const int* edge_index = (const int*)d_in[7];
    const int* pred_edges = (const int*)d_in[8];
    float* out = (float*)d_out;

    const int* src = edge_index;
    const int* dst = edge_index + EE;
    const int* ps = pred_edges;
    const int* pd = pred_edges + EPP;

    static int attr_done = 0;
    if (!attr_done) {
        cudaFuncSetAttribute(k_mm, cudaFuncAttributeMaxDynamicSharedMemorySize, SMEM_MM);
        attr_done = 1;
    }

    k_zero_deg<<<(NN + 255) / 256, 256>>>();
    k_count<<<(EE + 255) / 256, 256>>>(dst);
    k_scan<<<1, 1024>>>();
    k_fill<<<(EE + 255) / 256, 256>>>(src, dst);
    k_prepackW<<<(2 * DIM * KK + 255) / 256, 256>>>(W1l, W1r, W2l, W2r);

    k_agg<<<(NN * 32 + 255) / 256, 256>>>(x, 0);
    k_mm<<<MTILES, 256, SMEM_MM>>>(b1, 1);
    k_agg<<<(NN * 32 + 255) / 256, 256>>>(nullptr, 1);
    k_mm<<<MTILES, 256, SMEM_MM>>>(b2, 2);
    k_pred<<<(EPP * 32 + 255) / 256, 256>>>(ps, pd, out);
}